// round 1
// baseline (speedup 1.0000x reference)
#include <cuda_runtime.h>
#include <cuda_bf16.h>
#include <cstdint>

#define NN   2048      // nodes
#define DD   256       // embedding size
#define CC   768       // cat size
#define VV   2         // variants
#define LL   16        // activities per variant
#define EMAX 32768     // 16*N edges

// ---------------- scratch (device globals; no allocation allowed) ----------------
__device__ float g_emb[2][VV][NN * DD];     // ping-pong per variant
__device__ float g_msg[VV][NN * DD];
__device__ float g_pi[VV][NN * CC];
__device__ float g_summary[VV][CC];
__device__ float g_delta[VV][CC];
__device__ int   g_maskedList[VV][NN];
__device__ int   g_maskedCnt[VV];
__device__ int   g_act[VV][LL];
__device__ int   g_later[VV][LL][LL];
__device__ int   g_laterCnt[VV][LL];
__device__ int   g_has[VV][LL];
__device__ int   g_csrCnt[NN];
__device__ int   g_csrOff[NN + 1];
__device__ int   g_csrCur[NN];
__device__ int   g_csrSrc[EMAX];

// ---------------- init: copy embeddings, zero pi / csr counts ----------------
__global__ void init_k(const float* __restrict__ embeddings) {
    int t0 = blockIdx.x * blockDim.x + threadIdx.x;
    int stride = gridDim.x * blockDim.x;
    for (int idx = t0; idx < NN * DD; idx += stride) {
        float e = embeddings[idx];
        g_emb[0][0][idx] = e;
        g_emb[0][1][idx] = e;
    }
    for (int idx = t0; idx < VV * NN * CC; idx += stride) {
        ((float*)g_pi)[idx] = 0.0f;
    }
    for (int idx = t0; idx < NN; idx += stride) g_csrCnt[idx] = 0;
}

// ---------------- prep: per-(v,i) activity, distinct later-set, has flag ----------------
__global__ void prep_k(const int* __restrict__ variants, const int* __restrict__ adj) {
    int t = threadIdx.x;                 // 1024 threads
    int w = t >> 5, lane = t & 31;
    if (w < VV * LL) {
        int v = w >> 4, i = w & 15;
        int a = variants[v * LL + i];
        if (lane == 0) {
            g_act[v][i] = a;
            int cnt = 0;
            for (int j = i + 1; j < LL; j++) {
                int nd = variants[v * LL + j];
                bool dup = false;
                for (int q = 0; q < cnt; q++) if (g_later[v][i][q] == nd) dup = true;
                if (!dup) g_later[v][i][cnt++] = nd;
            }
            g_laterCnt[v][i] = cnt;
        }
        int any = 0;
        for (int p = lane; p < NN; p += 32) any |= (adj[(size_t)a * NN + p] != 0);
        any = __any_sync(0xffffffffu, any);
        if (lane == 0) g_has[v][i] = any;
    }
    // zero summary / delta / masked counters
    for (int idx = t; idx < VV * CC; idx += blockDim.x) {
        ((float*)g_summary)[idx] = 0.0f;
        ((float*)g_delta)[idx] = 0.0f;
    }
    if (t < VV) g_maskedCnt[t] = 0;
}

// ---------------- CSR build (dst-major) ----------------
__global__ void csr_count_k(const int* __restrict__ ei, int E) {
    int t0 = blockIdx.x * blockDim.x + threadIdx.x;
    int stride = gridDim.x * blockDim.x;
    for (int e = t0; e < E; e += stride) atomicAdd(&g_csrCnt[ei[E + e]], 1);
}

__global__ void csr_scan_k() {
    __shared__ int s[2][NN];
    int t = threadIdx.x;                 // 1024 threads
    s[0][t] = g_csrCnt[t];
    s[0][t + 1024] = g_csrCnt[t + 1024];
    __syncthreads();
    int src = 0;
    for (int off = 1; off < NN; off <<= 1) {
        int dstb = src ^ 1;
        for (int idx = t; idx < NN; idx += 1024) {
            int val = s[src][idx];
            if (idx >= off) val += s[src][idx - off];
            s[dstb][idx] = val;
        }
        __syncthreads();
        src = dstb;
    }
    for (int idx = t; idx < NN; idx += 1024) {
        int excl = (idx == 0) ? 0 : s[src][idx - 1];
        g_csrOff[idx] = excl;
        g_csrCur[idx] = excl;
    }
    if (t == 0) g_csrOff[NN] = s[src][NN - 1];
}

__global__ void csr_fill_k(const int* __restrict__ ei, int E) {
    int t0 = blockIdx.x * blockDim.x + threadIdx.x;
    int stride = gridDim.x * blockDim.x;
    for (int e = t0; e < E; e += stride) {
        int dst = ei[E + e];
        int pos = atomicAdd(&g_csrCur[dst], 1);
        g_csrSrc[pos] = ei[e];
    }
}

// ---------------- step A: mask, dst_all, pi += cat, delta += pi_new ----------------
__global__ __launch_bounds__(192) void stepA_k(const int* __restrict__ adj, int i, int cur) {
    int p = blockIdx.x, v = blockIdx.y;
    if (!g_has[v][i]) return;
    int a = g_act[v][i];
    if (adj[(size_t)a * NN + p] == 0) return;     // not a follower of a
    int cnt = g_laterCnt[v][i];
    const float* emb = g_emb[cur][v];
    int t = threadIdx.x;                           // 192 threads: 768 floats as float4

    float4 catv = make_float4(0.f, 0.f, 0.f, 0.f);
    if (t < 64)        catv = *(const float4*)&emb[(size_t)p * DD + t * 4];
    else if (t < 128)  catv = *(const float4*)&emb[(size_t)a * DD + (t - 64) * 4];

    int dest = 0;
    for (int q = 0; q < cnt; q++) {
        int lk = g_later[v][i][q];
        if (adj[(size_t)p * NN + lk] != 0) {
            dest = 1;
            if (t >= 128) {
                const float4 s = *(const float4*)&emb[(size_t)lk * DD + (t - 128) * 4];
                catv.x += s.x; catv.y += s.y; catv.z += s.z; catv.w += s.w;
            }
        }
    }
    if (!dest) return;                             // uniform across block

    float* pir = &g_pi[v][(size_t)p * CC];
    float4 old = *(float4*)&pir[t * 4];
    float4 nw = make_float4(old.x + catv.x, old.y + catv.y, old.z + catv.z, old.w + catv.w);
    *(float4*)&pir[t * 4] = nw;
    float* del = g_delta[v];
    atomicAdd(&del[t * 4 + 0], nw.x);
    atomicAdd(&del[t * 4 + 1], nw.y);
    atomicAdd(&del[t * 4 + 2], nw.z);
    atomicAdd(&del[t * 4 + 3], nw.w);
    if (t == 0) {
        int idx = atomicAdd(&g_maskedCnt[v], 1);
        if (idx < NN) g_maskedList[v][idx] = p;
    }
}

// ---------------- step B: pi[masked] += (summary_old + delta) ----------------
__global__ __launch_bounds__(192) void stepB_k(int i) {
    int v = blockIdx.y;
    if (!g_has[v][i]) return;
    int m = blockIdx.x;
    if (m >= g_maskedCnt[v]) return;
    int p = g_maskedList[v][m];
    int t = threadIdx.x;
    float4 s = *(float4*)&g_summary[v][t * 4];
    float4 d = *(float4*)&g_delta[v][t * 4];
    float* pir = &g_pi[v][(size_t)p * CC];
    float4 o = *(float4*)&pir[t * 4];
    o.x += s.x + d.x; o.y += s.y + d.y; o.z += s.z + d.z; o.w += s.w + d.w;
    *(float4*)&pir[t * 4] = o;
}

// ---------------- step C: summary += delta; delta = 0; masked reset ----------------
__global__ __launch_bounds__(192) void stepC_k() {
    int v = blockIdx.x;
    int t = threadIdx.x;
    float4 d = *(float4*)&g_delta[v][t * 4];
    float4 s = *(float4*)&g_summary[v][t * 4];
    s.x += d.x; s.y += d.y; s.z += d.z; s.w += d.w;
    *(float4*)&g_summary[v][t * 4] = s;
    *(float4*)&g_delta[v][t * 4] = make_float4(0.f, 0.f, 0.f, 0.f);
    if (t == 0) g_maskedCnt[v] = 0;
}

// ---------------- msg = segment_sum over CSR ----------------
__global__ __launch_bounds__(64) void msg_k(int i, int cur) {
    int dst = blockIdx.x, v = blockIdx.y;
    if (!g_has[v][i]) return;
    const float4* emb4 = (const float4*)g_emb[cur][v];
    int t = threadIdx.x;                           // 64 threads x float4 = 256 cols
    float4 acc = make_float4(0.f, 0.f, 0.f, 0.f);
    int s0 = g_csrOff[dst], s1 = g_csrOff[dst + 1];
#pragma unroll 4
    for (int j = s0; j < s1; j++) {
        int s = g_csrSrc[j];
        float4 e = emb4[(size_t)s * (DD / 4) + t];
        acc.x += e.x; acc.y += e.y; acc.z += e.z; acc.w += e.w;
    }
    ((float4*)g_msg[v])[(size_t)dst * (DD / 4) + t] = acc;
}

// ---------------- encoder GEMM: out = relu([emb|msg] @ [Wself;Wnbr] + b) ----------------
// BM=64, BN=64, BK=16, 128 threads, thread tile 8x4
__global__ __launch_bounds__(128) void enc_gemm_k(
    const float* __restrict__ Wself, const float* __restrict__ Wnbr,
    const float* __restrict__ bias, int i, int cur)
{
    int v = blockIdx.z;
    int m0 = blockIdx.x * 64;
    int n0 = blockIdx.y * 64;
    const float* X = g_emb[cur][v];
    float* O = g_emb[cur ^ 1][v];
    int t = threadIdx.x;

    if (!g_has[v][i]) {
        // encoder skipped: emb passes through
        int c = (t & 15) * 4;
        for (int r = (t >> 4); r < 64; r += 8) {
            *(float4*)&O[(size_t)(m0 + r) * DD + n0 + c] =
                *(const float4*)&X[(size_t)(m0 + r) * DD + n0 + c];
        }
        return;
    }

    const float* Msg = g_msg[v];
    __shared__ float As[16][64];
    __shared__ float Bs[16][64];

    float acc[8][4];
#pragma unroll
    for (int um = 0; um < 8; um++)
#pragma unroll
        for (int un = 0; un < 4; un++) acc[um][un] = 0.f;

    int tm = t >> 4;          // 0..7
    int tn = t & 15;          // 0..15
    int lar = t >> 1;         // 0..63   (A loader row)
    int lac = (t & 1) * 8;    // 0 or 8  (A loader col offset)
    int lbr = t >> 3;         // 0..15   (B loader row)
    int lbc = (t & 7) * 8;    // 0..56   (B loader col offset)

    for (int kt = 0; kt < 512; kt += 16) {
        const float* Asrc = (kt < 256) ? X : Msg;
        const float* Bsrc = (kt < 256) ? Wself : Wnbr;
        int kcol = kt & 255;

        float4 a0 = *(const float4*)&Asrc[(size_t)(m0 + lar) * DD + kcol + lac];
        float4 a1 = *(const float4*)&Asrc[(size_t)(m0 + lar) * DD + kcol + lac + 4];
        As[lac + 0][lar] = a0.x; As[lac + 1][lar] = a0.y;
        As[lac + 2][lar] = a0.z; As[lac + 3][lar] = a0.w;
        As[lac + 4][lar] = a1.x; As[lac + 5][lar] = a1.y;
        As[lac + 6][lar] = a1.z; As[lac + 7][lar] = a1.w;

        int brow = kcol + lbr;
        float4 b0 = *(const float4*)&Bsrc[(size_t)brow * DD + n0 + lbc];
        float4 b1 = *(const float4*)&Bsrc[(size_t)brow * DD + n0 + lbc + 4];
        *(float4*)&Bs[lbr][lbc] = b0;
        *(float4*)&Bs[lbr][lbc + 4] = b1;

        __syncthreads();
#pragma unroll
        for (int k = 0; k < 16; k++) {
            float ra[8], rb[4];
            *(float4*)&ra[0] = *(float4*)&As[k][tm * 8];
            *(float4*)&ra[4] = *(float4*)&As[k][tm * 8 + 4];
            *(float4*)&rb[0] = *(float4*)&Bs[k][tn * 4];
#pragma unroll
            for (int um = 0; um < 8; um++)
#pragma unroll
                for (int un = 0; un < 4; un++)
                    acc[um][un] = fmaf(ra[um], rb[un], acc[um][un]);
        }
        __syncthreads();
    }

    float4 bb = *(const float4*)&bias[n0 + tn * 4];
#pragma unroll
    for (int um = 0; um < 8; um++) {
        float4 o;
        o.x = fmaxf(acc[um][0] + bb.x, 0.f);
        o.y = fmaxf(acc[um][1] + bb.y, 0.f);
        o.z = fmaxf(acc[um][2] + bb.z, 0.f);
        o.w = fmaxf(acc[um][3] + bb.w, 0.f);
        *(float4*)&O[(size_t)(m0 + tm * 8 + um) * DD + n0 + tn * 4] = o;
    }
}

// ---------------- final: out = pi[0] + pi[1] ----------------
__global__ void sum_out_k(float* __restrict__ out) {
    int t0 = blockIdx.x * blockDim.x + threadIdx.x;
    int stride = gridDim.x * blockDim.x;
    const float* p0 = g_pi[0];
    const float* p1 = g_pi[1];
    for (int idx = t0; idx < NN * CC; idx += stride) out[idx] = p0[idx] + p1[idx];
}

// ---------------- launch ----------------
extern "C" void kernel_launch(void* const* d_in, const int* in_sizes, int n_in,
                              void* d_out, int out_size) {
    const float* embeddings = (const float*)d_in[0];
    const float* Wself      = (const float*)d_in[1];
    const float* Wnbr       = (const float*)d_in[2];
    const float* bvec       = (const float*)d_in[3];
    const int*   variants   = (const int*)d_in[4];
    const int*   original   = (const int*)d_in[5];
    const int*   edge_index = (const int*)d_in[6];
    float* out = (float*)d_out;
    int E = in_sizes[6] / 2;

    init_k<<<512, 256>>>(embeddings);
    prep_k<<<1, 1024>>>(variants, original);
    csr_count_k<<<128, 256>>>(edge_index, E);
    csr_scan_k<<<1, 1024>>>();
    csr_fill_k<<<128, 256>>>(edge_index, E);

    int cur = 0;
    for (int i = 0; i < LL; i++) {
        stepA_k<<<dim3(NN, VV), 192>>>(original, i, cur);
        stepB_k<<<dim3(512, VV), 192>>>(i);
        stepC_k<<<VV, 192>>>();
        msg_k<<<dim3(NN, VV), 64>>>(i, cur);
        enc_gemm_k<<<dim3(32, 4, VV), 128>>>(Wself, Wnbr, bvec, i, cur);
        cur ^= 1;
    }

    sum_out_k<<<1024, 256>>>(out);
}

// round 2
// speedup vs baseline: 1.6058x; 1.6058x over previous
#include <cuda_runtime.h>
#include <cuda_bf16.h>
#include <cstdint>

#define NN   2048      // nodes
#define DD   256       // embedding size
#define CC   768       // cat size
#define VV   2         // variants
#define LL   16        // activities per variant
#define EMAX 32768     // 16*N edges

// ---------------- scratch (device globals; no allocation allowed) ----------------
__device__ float g_emb[2][VV][NN * DD];     // ping-pong per variant
__device__ float g_msg[VV][NN * DD];
__device__ float g_pi[VV][NN * CC];
__device__ float g_summary[VV][2][CC];      // parity ping-pong
__device__ float g_delta[VV][2][CC];
__device__ int   g_maskedList[VV][NN];
__device__ int   g_maskedCnt[VV][2];
__device__ int   g_act[VV][LL];
__device__ int   g_later[VV][LL][LL];
__device__ int   g_laterCnt[VV][LL];
__device__ int   g_has[VV][LL];
__device__ int   g_csrCnt[NN];
__device__ int   g_csrOff[NN + 1];
__device__ int   g_csrCur[NN];
__device__ int   g_csrSrc[EMAX];
// W stacked [Wself;Wnbr] transposed: [N=256][K=512], bf16 hi/lo split
__device__ __nv_bfloat16 g_Wt_hi[DD * 2 * DD];
__device__ __nv_bfloat16 g_Wt_lo[DD * 2 * DD];

// ---------------- init: copy embeddings, zero pi / csr counts ----------------
__global__ void init_k(const float* __restrict__ embeddings) {
    int t0 = blockIdx.x * blockDim.x + threadIdx.x;
    int stride = gridDim.x * blockDim.x;
    for (int idx = t0; idx < NN * DD; idx += stride) {
        float e = embeddings[idx];
        g_emb[0][0][idx] = e;
        g_emb[0][1][idx] = e;
    }
    for (int idx = t0; idx < VV * NN * CC; idx += stride) {
        ((float*)g_pi)[idx] = 0.0f;
    }
    for (int idx = t0; idx < NN; idx += stride) g_csrCnt[idx] = 0;
}

// ---------------- W convert+transpose (once): bf16 hi/lo ----------------
__global__ void wconv_k(const float* __restrict__ Wself, const float* __restrict__ Wnbr) {
    int t0 = blockIdx.x * blockDim.x + threadIdx.x;
    int stride = gridDim.x * blockDim.x;
    for (int idx = t0; idx < DD * 2 * DD; idx += stride) {
        int n = idx >> 9;           // 0..255
        int k = idx & 511;          // 0..511
        float w = (k < DD) ? Wself[k * DD + n] : Wnbr[(k - DD) * DD + n];
        __nv_bfloat16 hi = __float2bfloat16(w);
        __nv_bfloat16 lo = __float2bfloat16(w - __bfloat162float(hi));
        g_Wt_hi[n * 512 + k] = hi;
        g_Wt_lo[n * 512 + k] = lo;
    }
}

// ---------------- prep: per-(v,i) activity, distinct later-set, has flag ----------------
__global__ void prep_k(const int* __restrict__ variants, const int* __restrict__ adj) {
    int t = threadIdx.x;                 // 1024 threads
    int w = t >> 5, lane = t & 31;
    if (w < VV * LL) {
        int v = w >> 4, i = w & 15;
        int a = variants[v * LL + i];
        if (lane == 0) {
            g_act[v][i] = a;
            int cnt = 0;
            for (int j = i + 1; j < LL; j++) {
                int nd = variants[v * LL + j];
                bool dup = false;
                for (int q = 0; q < cnt; q++) if (g_later[v][i][q] == nd) dup = true;
                if (!dup) g_later[v][i][cnt++] = nd;
            }
            g_laterCnt[v][i] = cnt;
        }
        int any = 0;
        for (int p = lane; p < NN; p += 32) any |= (adj[(size_t)a * NN + p] != 0);
        any = __any_sync(0xffffffffu, any);
        if (lane == 0) g_has[v][i] = any;
    }
    // zero summary / delta / masked counters (both parities)
    for (int idx = t; idx < VV * 2 * CC; idx += blockDim.x) {
        ((float*)g_summary)[idx] = 0.0f;
        ((float*)g_delta)[idx] = 0.0f;
    }
    if (t < VV * 2) ((int*)g_maskedCnt)[t] = 0;
}

// ---------------- CSR build (dst-major) ----------------
__global__ void csr_count_k(const int* __restrict__ ei, int E) {
    int t0 = blockIdx.x * blockDim.x + threadIdx.x;
    int stride = gridDim.x * blockDim.x;
    for (int e = t0; e < E; e += stride) atomicAdd(&g_csrCnt[ei[E + e]], 1);
}

__global__ void csr_scan_k() {
    __shared__ int s[2][NN];
    int t = threadIdx.x;                 // 1024 threads
    s[0][t] = g_csrCnt[t];
    s[0][t + 1024] = g_csrCnt[t + 1024];
    __syncthreads();
    int src = 0;
    for (int off = 1; off < NN; off <<= 1) {
        int dstb = src ^ 1;
        for (int idx = t; idx < NN; idx += 1024) {
            int val = s[src][idx];
            if (idx >= off) val += s[src][idx - off];
            s[dstb][idx] = val;
        }
        __syncthreads();
        src = dstb;
    }
    for (int idx = t; idx < NN; idx += 1024) {
        int excl = (idx == 0) ? 0 : s[src][idx - 1];
        g_csrOff[idx] = excl;
        g_csrCur[idx] = excl;
    }
    if (t == 0) g_csrOff[NN] = s[src][NN - 1];
}

__global__ void csr_fill_k(const int* __restrict__ ei, int E) {
    int t0 = blockIdx.x * blockDim.x + threadIdx.x;
    int stride = gridDim.x * blockDim.x;
    for (int e = t0; e < E; e += stride) {
        int dst = ei[E + e];
        int pos = atomicAdd(&g_csrCur[dst], 1);
        g_csrSrc[pos] = ei[e];
    }
}

// ---------------- step A: mask, dst_all, pi += cat, delta += pi_new ----------------
__global__ __launch_bounds__(192) void stepA_k(const int* __restrict__ adj, int i, int cur, int par) {
    int p = blockIdx.x, v = blockIdx.y;
    if (!g_has[v][i]) return;
    int a = g_act[v][i];
    if (adj[(size_t)a * NN + p] == 0) return;     // not a follower of a
    int cnt = g_laterCnt[v][i];
    const float* emb = g_emb[cur][v];
    int t = threadIdx.x;                           // 192 threads: 768 floats as float4

    float4 catv = make_float4(0.f, 0.f, 0.f, 0.f);
    if (t < 64)        catv = *(const float4*)&emb[(size_t)p * DD + t * 4];
    else if (t < 128)  catv = *(const float4*)&emb[(size_t)a * DD + (t - 64) * 4];

    int dest = 0;
    for (int q = 0; q < cnt; q++) {
        int lk = g_later[v][i][q];
        if (adj[(size_t)p * NN + lk] != 0) {
            dest = 1;
            if (t >= 128) {
                const float4 s = *(const float4*)&emb[(size_t)lk * DD + (t - 128) * 4];
                catv.x += s.x; catv.y += s.y; catv.z += s.z; catv.w += s.w;
            }
        }
    }
    if (!dest) return;                             // uniform across block

    float* pir = &g_pi[v][(size_t)p * CC];
    float4 old = *(float4*)&pir[t * 4];
    float4 nw = make_float4(old.x + catv.x, old.y + catv.y, old.z + catv.z, old.w + catv.w);
    *(float4*)&pir[t * 4] = nw;
    float* del = g_delta[v][par];
    atomicAdd(&del[t * 4 + 0], nw.x);
    atomicAdd(&del[t * 4 + 1], nw.y);
    atomicAdd(&del[t * 4 + 2], nw.z);
    atomicAdd(&del[t * 4 + 3], nw.w);
    if (t == 0) {
        int idx = atomicAdd(&g_maskedCnt[v][par], 1);
        if (idx < NN) g_maskedList[v][idx] = p;
    }
}

// ---------------- step B+C fused: pi[masked] += (s_old+delta); s_new=s_old+delta ----------------
__global__ __launch_bounds__(192) void stepBC_k(int par) {
    int v = blockIdx.y;
    int t = threadIdx.x;
    if (blockIdx.x == 64) {
        // bookkeeping block: write next-parity state (no one reads it this step)
        float4 s = *(float4*)&g_summary[v][par][t * 4];
        float4 d = *(float4*)&g_delta[v][par][t * 4];
        s.x += d.x; s.y += d.y; s.z += d.z; s.w += d.w;
        *(float4*)&g_summary[v][par ^ 1][t * 4] = s;
        *(float4*)&g_delta[v][par ^ 1][t * 4] = make_float4(0.f, 0.f, 0.f, 0.f);
        if (t == 0) g_maskedCnt[v][par ^ 1] = 0;
        return;
    }
    int cnt = g_maskedCnt[v][par];
    if (cnt > NN) cnt = NN;
    if (cnt == 0) return;
    float4 s = *(float4*)&g_summary[v][par][t * 4];
    float4 d = *(float4*)&g_delta[v][par][t * 4];
    float4 sd = make_float4(s.x + d.x, s.y + d.y, s.z + d.z, s.w + d.w);
    for (int m = blockIdx.x; m < cnt; m += 64) {
        int p = g_maskedList[v][m];
        float* pir = &g_pi[v][(size_t)p * CC];
        float4 o = *(float4*)&pir[t * 4];
        o.x += sd.x; o.y += sd.y; o.z += sd.z; o.w += sd.w;
        *(float4*)&pir[t * 4] = o;
    }
}

// ---------------- msg = segment_sum over CSR ----------------
__global__ __launch_bounds__(64) void msg_k(int i, int cur) {
    int dst = blockIdx.x, v = blockIdx.y;
    if (!g_has[v][i]) return;
    const float4* emb4 = (const float4*)g_emb[cur][v];
    int t = threadIdx.x;                           // 64 threads x float4 = 256 cols
    float4 acc = make_float4(0.f, 0.f, 0.f, 0.f);
    int s0 = g_csrOff[dst], s1 = g_csrOff[dst + 1];
#pragma unroll 4
    for (int j = s0; j < s1; j++) {
        int s = g_csrSrc[j];
        float4 e = emb4[(size_t)s * (DD / 4) + t];
        acc.x += e.x; acc.y += e.y; acc.z += e.z; acc.w += e.w;
    }
    ((float4*)g_msg[v])[(size_t)dst * (DD / 4) + t] = acc;
}

// ---------------- encoder GEMM (tensor cores, bf16x3) ----------------
// out = relu([emb|msg] @ Wt^T + b), M=4096 (both variants), N=256, K=512
// BM=128, BN=64, BK=32, 256 threads, 8 warps (4M x 2N), warp tile 32x32
#define SA 40   // As row stride (bf16) — conflict-free frag reads
#define SB 40

__device__ __forceinline__ void mma16816(float* c, const uint32_t* a, const uint32_t* b) {
    asm volatile(
        "mma.sync.aligned.m16n8k16.row.col.f32.bf16.bf16.f32 "
        "{%0,%1,%2,%3}, {%4,%5,%6,%7}, {%8,%9}, {%0,%1,%2,%3};"
        : "+f"(c[0]), "+f"(c[1]), "+f"(c[2]), "+f"(c[3])
        : "r"(a[0]), "r"(a[1]), "r"(a[2]), "r"(a[3]), "r"(b[0]), "r"(b[1]));
}

__global__ __launch_bounds__(256) void enc_gemm_k(const float* __restrict__ bias, int i, int cur) {
    int m0g = blockIdx.x * 128;          // global row (0..4095)
    int v = m0g >> 11;                   // variant
    int m0 = m0g & 2047;                 // row within variant
    int n0 = blockIdx.y * 64;
    const float* X = g_emb[cur][v];
    float* O = g_emb[cur ^ 1][v];
    int t = threadIdx.x;

    if (!g_has[v][i]) {
        // encoder skipped: emb passes through
        int r = t >> 1, ch = (t & 1) * 32;
#pragma unroll
        for (int j = 0; j < 8; j++) {
            *(float4*)&O[(size_t)(m0 + r) * DD + n0 + ch + j * 4] =
                *(const float4*)&X[(size_t)(m0 + r) * DD + n0 + ch + j * 4];
        }
        return;
    }

    const float* Msg = g_msg[v];
    __shared__ __align__(16) __nv_bfloat16 As[2][128][SA];   // [hi/lo]
    __shared__ __align__(16) __nv_bfloat16 Bs[2][64][SB];

    int lane = t & 31;
    int warp = t >> 5;
    int wm = warp >> 1;                  // 0..3
    int wn = warp & 1;                   // 0..1
    int g = lane >> 2;                   // 0..7
    int tq = lane & 3;                   // 0..3

    float acc[2][4][4];
#pragma unroll
    for (int mt = 0; mt < 2; mt++)
#pragma unroll
        for (int nt = 0; nt < 4; nt++)
#pragma unroll
            for (int e = 0; e < 4; e++) acc[mt][nt][e] = 0.f;

    // loader indices
    int aq = t & 7;                      // float4 column group
    int ar0 = t >> 3;                    // 0..31
    int bn = t >> 2;                     // 0..63
    int bseg = t & 3;                    // 0..3

    for (int kt = 0; kt < 512; kt += 32) {
        // --- fill A tile (fp32 -> bf16 hi/lo split) ---
        const float* Asrc = (kt < 256) ? X : Msg;
        int colbase = (kt & 255) + aq * 4;
#pragma unroll
        for (int rr = 0; rr < 4; rr++) {
            int row = ar0 + rr * 32;
            float4 f = *(const float4*)&Asrc[(size_t)(m0 + row) * DD + colbase];
            __nv_bfloat162 h0 = __floats2bfloat162_rn(f.x, f.y);
            __nv_bfloat162 h1 = __floats2bfloat162_rn(f.z, f.w);
            __nv_bfloat162 l0 = __floats2bfloat162_rn(f.x - __bfloat162float(h0.x),
                                                      f.y - __bfloat162float(h0.y));
            __nv_bfloat162 l1 = __floats2bfloat162_rn(f.z - __bfloat162float(h1.x),
                                                      f.w - __bfloat162float(h1.y));
            *(__nv_bfloat162*)&As[0][row][aq * 4]     = h0;
            *(__nv_bfloat162*)&As[0][row][aq * 4 + 2] = h1;
            *(__nv_bfloat162*)&As[1][row][aq * 4]     = l0;
            *(__nv_bfloat162*)&As[1][row][aq * 4 + 2] = l1;
        }
        // --- fill B tile (pre-split bf16, transposed W) ---
        {
            size_t woff = (size_t)(n0 + bn) * 512 + kt + bseg * 8;
            *(uint4*)&Bs[0][bn][bseg * 8] = *(const uint4*)&g_Wt_hi[woff];
            *(uint4*)&Bs[1][bn][bseg * 8] = *(const uint4*)&g_Wt_lo[woff];
        }
        __syncthreads();

#pragma unroll
        for (int sub = 0; sub < 2; sub++) {
            int kb = sub * 16;
            uint32_t ah[2][4], al[2][4], bh[4][2], bl[4][2];
#pragma unroll
            for (int mt = 0; mt < 2; mt++) {
                int r = wm * 32 + mt * 16 + g;
                ah[mt][0] = *(const uint32_t*)&As[0][r][kb + tq * 2];
                ah[mt][1] = *(const uint32_t*)&As[0][r + 8][kb + tq * 2];
                ah[mt][2] = *(const uint32_t*)&As[0][r][kb + tq * 2 + 8];
                ah[mt][3] = *(const uint32_t*)&As[0][r + 8][kb + tq * 2 + 8];
                al[mt][0] = *(const uint32_t*)&As[1][r][kb + tq * 2];
                al[mt][1] = *(const uint32_t*)&As[1][r + 8][kb + tq * 2];
                al[mt][2] = *(const uint32_t*)&As[1][r][kb + tq * 2 + 8];
                al[mt][3] = *(const uint32_t*)&As[1][r + 8][kb + tq * 2 + 8];
            }
#pragma unroll
            for (int nt = 0; nt < 4; nt++) {
                int n = wn * 32 + nt * 8 + g;
                bh[nt][0] = *(const uint32_t*)&Bs[0][n][kb + tq * 2];
                bh[nt][1] = *(const uint32_t*)&Bs[0][n][kb + tq * 2 + 8];
                bl[nt][0] = *(const uint32_t*)&Bs[1][n][kb + tq * 2];
                bl[nt][1] = *(const uint32_t*)&Bs[1][n][kb + tq * 2 + 8];
            }
#pragma unroll
            for (int mt = 0; mt < 2; mt++)
#pragma unroll
                for (int nt = 0; nt < 4; nt++) {
                    mma16816(acc[mt][nt], ah[mt], bh[nt]);
                    mma16816(acc[mt][nt], ah[mt], bl[nt]);
                    mma16816(acc[mt][nt], al[mt], bh[nt]);
                }
        }
        __syncthreads();
    }

    // epilogue: + bias, relu, store fp32
#pragma unroll
    for (int mt = 0; mt < 2; mt++) {
        int row = m0 + wm * 32 + mt * 16 + g;
#pragma unroll
        for (int nt = 0; nt < 4; nt++) {
            int col = n0 + wn * 32 + nt * 8 + tq * 2;
            float b0 = bias[col], b1 = bias[col + 1];
            float2 o0, o1;
            o0.x = fmaxf(acc[mt][nt][0] + b0, 0.f);
            o0.y = fmaxf(acc[mt][nt][1] + b1, 0.f);
            o1.x = fmaxf(acc[mt][nt][2] + b0, 0.f);
            o1.y = fmaxf(acc[mt][nt][3] + b1, 0.f);
            *(float2*)&O[(size_t)row * DD + col] = o0;
            *(float2*)&O[(size_t)(row + 8) * DD + col] = o1;
        }
    }
}

// ---------------- final: out = pi[0] + pi[1] ----------------
__global__ void sum_out_k(float* __restrict__ out) {
    int t0 = blockIdx.x * blockDim.x + threadIdx.x;
    int stride = gridDim.x * blockDim.x;
    const float* p0 = g_pi[0];
    const float* p1 = g_pi[1];
    for (int idx = t0; idx < NN * CC; idx += stride) out[idx] = p0[idx] + p1[idx];
}

// ---------------- launch ----------------
extern "C" void kernel_launch(void* const* d_in, const int* in_sizes, int n_in,
                              void* d_out, int out_size) {
    const float* embeddings = (const float*)d_in[0];
    const float* Wself      = (const float*)d_in[1];
    const float* Wnbr       = (const float*)d_in[2];
    const float* bvec       = (const float*)d_in[3];
    const int*   variants   = (const int*)d_in[4];
    const int*   original   = (const int*)d_in[5];
    const int*   edge_index = (const int*)d_in[6];
    float* out = (float*)d_out;
    int E = in_sizes[6] / 2;

    init_k<<<512, 256>>>(embeddings);
    wconv_k<<<256, 256>>>(Wself, Wnbr);
    prep_k<<<1, 1024>>>(variants, original);
    csr_count_k<<<128, 256>>>(edge_index, E);
    csr_scan_k<<<1, 1024>>>();
    csr_fill_k<<<128, 256>>>(edge_index, E);

    int cur = 0;
    for (int i = 0; i < LL; i++) {
        stepA_k<<<dim3(NN, VV), 192>>>(original, i, cur, i & 1);
        stepBC_k<<<dim3(65, VV), 192>>>(i & 1);
        msg_k<<<dim3(NN, VV), 64>>>(i, cur);
        enc_gemm_k<<<dim3(32, 4), 256>>>(bvec, i, cur);
        cur ^= 1;
    }

    sum_out_k<<<1024, 256>>>(out);
}